// round 1
// baseline (speedup 1.0000x reference)
#include <cuda_runtime.h>
#include <math.h>

// LSTM cell: gates = [x | h_prev] @ [Wf|Wi|Wg|Wo] + b ; fused epilogue.
// B=4096, IN=1024, H=1024, K=2048. Output: [h_next (4096x1024), c_next (4096x1024)].
//
// Round 0 strategy: correct fp32 baseline at the FFMA2 (fma.rn.f32x2) roofline
// (~72 TF/s). CTA computes a 64(m) x 64(n) tile for ALL FOUR gates (4 fp32
// accumulator sets), then applies sigmoid/tanh epilogue in-register — gates
// matrix is never materialized.

#define BM 64
#define BN 64
#define BK 16
#define KTOT 2048
#define HDIM 1024

typedef unsigned long long ull;

__device__ __forceinline__ ull pk2(float lo, float hi) {
    ull r;
    asm("mov.b64 %0, {%1, %2};" : "=l"(r) : "f"(lo), "f"(hi));
    return r;
}
__device__ __forceinline__ void upk2(ull v, float &lo, float &hi) {
    asm("mov.b64 {%0, %1}, %2;" : "=f"(lo), "=f"(hi) : "l"(v));
}
// Packed dual-FMA: d.lo += a.lo*b.lo ; d.hi += a.hi*b.hi  (2x FFMA throughput)
__device__ __forceinline__ void ffma2(ull &d, ull a, ull b) {
    asm("fma.rn.f32x2 %0, %1, %2, %3;" : "=l"(d) : "l"(a), "l"(b), "l"(d));
}

__device__ __forceinline__ float sigmoidf(float v) {
    return 1.0f / (1.0f + expf(-v));
}

__global__ __launch_bounds__(256) void lstm_fused_kernel(
    const float* __restrict__ x, const float* __restrict__ h_prev,
    const float* __restrict__ c_prev,
    const float* __restrict__ Wf, const float* __restrict__ bf,
    const float* __restrict__ Wi, const float* __restrict__ bi,
    const float* __restrict__ Wg, const float* __restrict__ bg,
    const float* __restrict__ Wo, const float* __restrict__ bo,
    float* __restrict__ h_out, float* __restrict__ c_out)
{
    __shared__ float As[BK][BM];        // A tile, transposed: [k][m]   (4 KB)
    __shared__ float Bs[4][BK][BN];     // 4 gate weight tiles: [g][k][n] (16 KB)

    const int t  = threadIdx.x;
    const int m0 = blockIdx.y * BM;
    const int n0 = blockIdx.x * BN;

    // compute-thread mapping: 16x16 threads, each owns a 4(m) x 4(n) microtile
    const int tx = t & 15;        // n direction
    const int ty = t >> 4;        // m direction

    // A loader: thread -> (row, k-quad); conflict-free STS (lanes span 32 rows)
    const int ar = t & 63;        // m row within tile
    const int aq = t >> 6;        // which group of 4 k-columns (0..3)
    // B loader: thread -> (k-row, n-quad); coalesced LDG + conflict-free STS.128
    const int bkr = t >> 4;       // k row (0..15)
    const int bc4 = t & 15;       // n float4 index (0..15)

    const float* const Wp[4] = {Wf, Wi, Wg, Wo};

    // Accumulators: [gate][mi][n-pair] as packed f32x2 (64 fp32 values/thread)
    ull acc[4][4][2];
    #pragma unroll
    for (int g = 0; g < 4; g++)
        #pragma unroll
        for (int mi = 0; mi < 4; mi++) {
            acc[g][mi][0] = 0ULL;
            acc[g][mi][1] = 0ULL;
        }

    for (int kb = 0; kb < KTOT / BK; kb++) {
        const int k0 = kb * BK;
        // combined = [x | h_prev]: k < 1024 reads x, else h_prev
        const float* Asrc = (kb < 64) ? x : h_prev;
        const int k0c = (kb & 63) * BK;

        // stage global loads in registers
        float4 av = *reinterpret_cast<const float4*>(
            &Asrc[(size_t)(m0 + ar) * HDIM + k0c + aq * 4]);
        float4 bv[4];
        #pragma unroll
        for (int g = 0; g < 4; g++)
            bv[g] = *reinterpret_cast<const float4*>(
                &Wp[g][(size_t)(k0 + bkr) * HDIM + n0 + bc4 * 4]);

        __syncthreads();   // previous iteration's compute done reading smem

        // scatter A transposed
        As[aq * 4 + 0][ar] = av.x;
        As[aq * 4 + 1][ar] = av.y;
        As[aq * 4 + 2][ar] = av.z;
        As[aq * 4 + 3][ar] = av.w;
        // store B tiles
        #pragma unroll
        for (int g = 0; g < 4; g++)
            *reinterpret_cast<float4*>(&Bs[g][bkr][bc4 * 4]) = bv[g];

        __syncthreads();

        #pragma unroll
        for (int kk = 0; kk < BK; kk++) {
            float4 a = *reinterpret_cast<const float4*>(&As[kk][ty * 4]);
            ull a2[4];
            a2[0] = pk2(a.x, a.x);
            a2[1] = pk2(a.y, a.y);
            a2[2] = pk2(a.z, a.z);
            a2[3] = pk2(a.w, a.w);
            #pragma unroll
            for (int g = 0; g < 4; g++) {
                float4 b = *reinterpret_cast<const float4*>(&Bs[g][kk][tx * 4]);
                ull b01 = pk2(b.x, b.y);
                ull b23 = pk2(b.z, b.w);
                #pragma unroll
                for (int mi = 0; mi < 4; mi++) {
                    ffma2(acc[g][mi][0], a2[mi], b01);
                    ffma2(acc[g][mi][1], a2[mi], b23);
                }
            }
        }
    }

    // ---- fused LSTM epilogue ----
    const int nbase = n0 + tx * 4;
    float bF[4], bI[4], bG[4], bO[4];
    #pragma unroll
    for (int ni = 0; ni < 4; ni++) {
        bF[ni] = bf[nbase + ni];
        bI[ni] = bi[nbase + ni];
        bG[ni] = bg[nbase + ni];
        bO[ni] = bo[nbase + ni];
    }

    #pragma unroll
    for (int mi = 0; mi < 4; mi++) {
        const int m = m0 + ty * 4 + mi;
        float vF[4], vI[4], vG[4], vO[4];
        upk2(acc[0][mi][0], vF[0], vF[1]); upk2(acc[0][mi][1], vF[2], vF[3]);
        upk2(acc[1][mi][0], vI[0], vI[1]); upk2(acc[1][mi][1], vI[2], vI[3]);
        upk2(acc[2][mi][0], vG[0], vG[1]); upk2(acc[2][mi][1], vG[2], vG[3]);
        upk2(acc[3][mi][0], vO[0], vO[1]); upk2(acc[3][mi][1], vO[2], vO[3]);

        float4 cp = *reinterpret_cast<const float4*>(&c_prev[(size_t)m * HDIM + nbase]);
        float cpv[4] = {cp.x, cp.y, cp.z, cp.w};

        float hn[4], cn[4];
        #pragma unroll
        for (int ni = 0; ni < 4; ni++) {
            float fg = sigmoidf(vF[ni] + bF[ni]);
            float ig = sigmoidf(vI[ni] + bI[ni]);
            float gg = tanhf(vG[ni] + bG[ni]);
            float og = sigmoidf(vO[ni] + bO[ni]);
            float c  = fg * cpv[ni] + ig * gg;
            cn[ni] = c;
            hn[ni] = og * tanhf(c);
        }
        *reinterpret_cast<float4*>(&h_out[(size_t)m * HDIM + nbase]) =
            make_float4(hn[0], hn[1], hn[2], hn[3]);
        *reinterpret_cast<float4*>(&c_out[(size_t)m * HDIM + nbase]) =
            make_float4(cn[0], cn[1], cn[2], cn[3]);
    }
}

extern "C" void kernel_launch(void* const* d_in, const int* in_sizes, int n_in,
                              void* d_out, int out_size) {
    const float* x      = (const float*)d_in[0];
    const float* h_prev = (const float*)d_in[1];
    const float* c_prev = (const float*)d_in[2];
    const float* Wf     = (const float*)d_in[3];
    const float* bf     = (const float*)d_in[4];
    const float* Wi     = (const float*)d_in[5];
    const float* bi     = (const float*)d_in[6];
    const float* Wg     = (const float*)d_in[7];
    const float* bg     = (const float*)d_in[8];
    const float* Wo     = (const float*)d_in[9];
    const float* bo     = (const float*)d_in[10];

    float* out   = (float*)d_out;
    float* h_out = out;
    float* c_out = out + (size_t)out_size / 2;   // (h_next, c_next) flattened in order

    dim3 grid(HDIM / BN, 4096 / BM);   // (16, 64)
    lstm_fused_kernel<<<grid, 256>>>(x, h_prev, c_prev,
                                     Wf, bf, Wi, bi, Wg, bg, Wo, bo,
                                     h_out, c_out);
}

// round 3
// speedup vs baseline: 2.5976x; 2.5976x over previous
#include <cuda_runtime.h>
#include <cuda_bf16.h>
#include <math.h>

#define B_DIM 4096
#define H_DIM 1024
#define K_DIM 2048

// GEMM tiling: C[4096 m][4096 n'] where n' = n*4 + gate (gate-interleaved)
#define BM 128
#define BNP 128              // n' columns per CTA
#define BK 32                // k per stage
#define KSTAGES (K_DIM / BK) // 64

// ---------------- device scratch (allocation-free rule: __device__ globals) ----
__device__ __align__(1024) __nv_bfloat16 g_Ah[(size_t)B_DIM * K_DIM];
__device__ __align__(1024) __nv_bfloat16 g_Al[(size_t)B_DIM * K_DIM];
__device__ __align__(1024) __nv_bfloat16 g_Bh[(size_t)4 * H_DIM * K_DIM];
__device__ __align__(1024) __nv_bfloat16 g_Bl[(size_t)4 * H_DIM * K_DIM];

// ---------------- helpers ----------------
__device__ __forceinline__ unsigned smem_u32(const void* p) {
    unsigned a;
    asm("{ .reg .u64 t; cvta.to.shared.u64 t, %1; cvt.u32.u64 %0, t; }" : "=r"(a) : "l"(p));
    return a;
}
__device__ __forceinline__ void cpa16(unsigned dst, const void* src) {
    asm volatile("cp.async.cg.shared.global [%0], [%1], 16;" :: "r"(dst), "l"(src) : "memory");
}
#define CPA_COMMIT() asm volatile("cp.async.commit_group;" ::: "memory")
#define CPA_WAIT1()  asm volatile("cp.async.wait_group 1;" ::: "memory")
#define CPA_WAIT0()  asm volatile("cp.async.wait_group 0;" ::: "memory")

__device__ __forceinline__ void ldsm4(unsigned &r0, unsigned &r1, unsigned &r2, unsigned &r3,
                                      unsigned addr) {
    asm volatile("ldmatrix.sync.aligned.m8n8.x4.shared.b16 {%0,%1,%2,%3}, [%4];"
                 : "=r"(r0), "=r"(r1), "=r"(r2), "=r"(r3) : "r"(addr));
}
__device__ __forceinline__ void ldsm2(unsigned &r0, unsigned &r1, unsigned addr) {
    asm volatile("ldmatrix.sync.aligned.m8n8.x2.shared.b16 {%0,%1}, [%2];"
                 : "=r"(r0), "=r"(r1) : "r"(addr));
}
__device__ __forceinline__ void mma16816(float* c, const unsigned* a, const unsigned* b) {
    asm volatile(
        "mma.sync.aligned.m16n8k16.row.col.f32.bf16.bf16.f32 "
        "{%0,%1,%2,%3}, {%4,%5,%6,%7}, {%8,%9}, {%0,%1,%2,%3};"
        : "+f"(c[0]), "+f"(c[1]), "+f"(c[2]), "+f"(c[3])
        : "r"(a[0]), "r"(a[1]), "r"(a[2]), "r"(a[3]), "r"(b[0]), "r"(b[1]));
}

// ---------------- convert kernels ----------------
__global__ __launch_bounds__(256) void conv_a_kernel(const float* __restrict__ x,
                                                     const float* __restrict__ h_prev) {
    int m = blockIdx.x, t = threadIdx.x;
    int k = t * 8;
    const float* src = (k < H_DIM) ? (x + (size_t)m * H_DIM + k)
                                   : (h_prev + (size_t)m * H_DIM + (k - H_DIM));
    float4 v0 = *reinterpret_cast<const float4*>(src);
    float4 v1 = *reinterpret_cast<const float4*>(src + 4);
    float vs[8] = {v0.x, v0.y, v0.z, v0.w, v1.x, v1.y, v1.z, v1.w};
    __align__(16) __nv_bfloat16 hi[8], lo[8];
    #pragma unroll
    for (int j = 0; j < 8; j++) {
        hi[j] = __float2bfloat16(vs[j]);
        lo[j] = __float2bfloat16(vs[j] - __bfloat162float(hi[j]));
    }
    *reinterpret_cast<uint4*>(g_Ah + (size_t)m * K_DIM + k) = *reinterpret_cast<uint4*>(hi);
    *reinterpret_cast<uint4*>(g_Al + (size_t)m * K_DIM + k) = *reinterpret_cast<uint4*>(lo);
}

// transpose W[k][n] -> BT[(n*4+g)][k], split hi/lo
__global__ __launch_bounds__(256) void conv_w_kernel(const float* __restrict__ Wf,
                                                     const float* __restrict__ Wi,
                                                     const float* __restrict__ Wg,
                                                     const float* __restrict__ Wo) {
    __shared__ float s[32][65];
    int k0 = blockIdx.x * 32, n0 = blockIdx.y * 64, g = blockIdx.z;
    const float* W = (g == 0) ? Wf : (g == 1) ? Wi : (g == 2) ? Wg : Wo;
    int t = threadIdx.x;
    #pragma unroll
    for (int i = 0; i < 8; i++) {
        int idx = t + i * 256;
        int kr = idx >> 6, nc = idx & 63;
        s[kr][nc] = W[(size_t)(k0 + kr) * H_DIM + n0 + nc];
    }
    __syncthreads();
    #pragma unroll
    for (int i = 0; i < 8; i++) {
        int idx = t + i * 256;
        int nn = idx >> 5, kk = idx & 31;
        float v = s[kk][nn];
        __nv_bfloat16 hi = __float2bfloat16(v);
        __nv_bfloat16 lo = __float2bfloat16(v - __bfloat162float(hi));
        size_t r = (size_t)((n0 + nn) * 4 + g) * K_DIM + k0 + kk;
        g_Bh[r] = hi;
        g_Bl[r] = lo;
    }
}

// ---------------- smem stage layout ----------------
// 4 tiles per stage, each 128 rows x 64B (BK=32 bf16), XOR-swizzled:
//   phys_chunk = chunk ^ ((row>>1)&3), 16B chunks
#define OFF_AH 0
#define OFF_AL (8 * 1024)
#define OFF_BH (16 * 1024)
#define OFF_BL (24 * 1024)
#define STAGE_BYTES (32 * 1024)
#define SMEM_TOTAL (2 * STAGE_BYTES)

__device__ __forceinline__ void load_stage(unsigned base, int s, int m0, int np0, int t) {
    int r = t >> 1;
    int cpair = (t & 1) * 2;
    const __nv_bfloat16* pAh = g_Ah + (size_t)(m0 + r) * K_DIM + s * BK + cpair * 8;
    const __nv_bfloat16* pAl = g_Al + (size_t)(m0 + r) * K_DIM + s * BK + cpair * 8;
    const __nv_bfloat16* pBh = g_Bh + (size_t)(np0 + r) * K_DIM + s * BK + cpair * 8;
    const __nv_bfloat16* pBl = g_Bl + (size_t)(np0 + r) * K_DIM + s * BK + cpair * 8;
    unsigned rowoff = (unsigned)r * 64;
    unsigned sw = (unsigned)((r >> 1) & 3);
    #pragma unroll
    for (int j = 0; j < 2; j++) {
        unsigned phys = ((unsigned)(cpair + j) ^ sw) * 16;
        cpa16(base + OFF_AH + rowoff + phys, pAh + j * 8);
        cpa16(base + OFF_AL + rowoff + phys, pAl + j * 8);
        cpa16(base + OFF_BH + rowoff + phys, pBh + j * 8);
        cpa16(base + OFF_BL + rowoff + phys, pBl + j * 8);
    }
}

// ---------------- GEMM + fused LSTM epilogue ----------------
__global__ __launch_bounds__(256) void lstm_gemm_kernel(
    const float* __restrict__ c_prev,
    const float* __restrict__ bfp, const float* __restrict__ bip,
    const float* __restrict__ bgp, const float* __restrict__ bop,
    float* __restrict__ h_out, float* __restrict__ c_out)
{
    extern __shared__ char smem[];
    unsigned sb = smem_u32(smem);
    const int t = threadIdx.x;
    const int w = t >> 5, lane = t & 31;
    const int m0  = blockIdx.y * BM;
    const int np0 = blockIdx.x * BNP;

    const int wm = (w >> 2) * 64;      // warp m base within CTA (0 or 64)
    const int wn = (w & 3) * 32;       // warp n' base within CTA

    // lane decompositions for ldmatrix addressing
    const int lr  = lane & 15;          // A: row within 16
    const int lc  = lane >> 4;          // A: k-chunk select (0/1)
    const int lb  = lane & 7;           // B: row within 8
    const int lcb = (lane >> 3) & 1;    // B: k-chunk select (lanes 0-15 matter)
    const unsigned swA = (unsigned)((lr >> 1) & 3);
    const unsigned swB = (unsigned)((lb >> 1) & 3);

    // precomputed row byte-offsets (swizzle row-term folded into sw constants)
    unsigned aRow[4], bRow[4];
    #pragma unroll
    for (int mi = 0; mi < 4; mi++) aRow[mi] = (unsigned)(wm + mi * 16 + lr) * 64;
    #pragma unroll
    for (int ni = 0; ni < 4; ni++) bRow[ni] = (unsigned)(wn + ni * 8 + lb) * 64;

    float acc[4][4][4];
    #pragma unroll
    for (int mi = 0; mi < 4; mi++)
        #pragma unroll
        for (int ni = 0; ni < 4; ni++)
            #pragma unroll
            for (int j = 0; j < 4; j++) acc[mi][ni][j] = 0.0f;

    load_stage(sb, 0, m0, np0, t); CPA_COMMIT();
    load_stage(sb + STAGE_BYTES, 1, m0, np0, t); CPA_COMMIT();

    for (int s = 0; s < KSTAGES; s++) {
        if (s == KSTAGES - 1) CPA_WAIT0(); else CPA_WAIT1();
        __syncthreads();
        unsigned base = sb + (unsigned)(s & 1) * STAGE_BYTES;

        #pragma unroll
        for (int k16 = 0; k16 < 2; k16++) {
            const unsigned cA = ((unsigned)(k16 * 2 + lc) ^ swA) * 16;
            const unsigned cB = ((unsigned)(k16 * 2 + lcb) ^ swB) * 16;

            unsigned ah[4][4], al[4][4], bh[4][2], bl[4][2];
            #pragma unroll
            for (int ni = 0; ni < 4; ni++) {
                ldsm2(bh[ni][0], bh[ni][1], base + OFF_BH + bRow[ni] + cB);
                ldsm2(bl[ni][0], bl[ni][1], base + OFF_BL + bRow[ni] + cB);
            }
            #pragma unroll
            for (int mi = 0; mi < 4; mi++) {
                ldsm4(ah[mi][0], ah[mi][1], ah[mi][2], ah[mi][3], base + OFF_AH + aRow[mi] + cA);
                ldsm4(al[mi][0], al[mi][1], al[mi][2], al[mi][3], base + OFF_AL + aRow[mi] + cA);
            }
            #pragma unroll
            for (int mi = 0; mi < 4; mi++)
                #pragma unroll
                for (int ni = 0; ni < 4; ni++) {
                    mma16816(acc[mi][ni], ah[mi], bh[ni]);
                    mma16816(acc[mi][ni], ah[mi], bl[ni]);
                    mma16816(acc[mi][ni], al[mi], bh[ni]);
                }
        }
        __syncthreads();
        if (s + 2 < KSTAGES) {
            load_stage(sb + (unsigned)(s & 1) * STAGE_BYTES, s + 2, m0, np0, t);
            CPA_COMMIT();
        }
    }

    // ---- fused LSTM epilogue ----
    // n' tile of 8 per ni = 2 real n x 4 gates: cols (0,1)=f,i  (2,3)=g,o of n_even; (4..7) n_odd
    const int g8  = lane >> 2;      // row within 8
    const int tg  = lane & 3;
    const int odd = tg & 1;
    const int nsel = tg >> 1;

    // per-ni real n and biases
    const int nwbase = blockIdx.x * 32 + (w & 3) * 8;
    float biasF[4], biasI[4], biasG[4], biasO[4];
    int nout[4];
    #pragma unroll
    for (int ni = 0; ni < 4; ni++) {
        nout[ni] = nwbase + ni * 2 + nsel;
        biasF[ni] = bfp[nout[ni]];
        biasI[ni] = bip[nout[ni]];
        biasG[ni] = bgp[nout[ni]];
        biasO[ni] = bop[nout[ni]];
    }

    #pragma unroll
    for (int mi = 0; mi < 4; mi++) {
        const int rbase = m0 + wm + mi * 16 + g8;
        const int row = rbase + (odd ? 8 : 0);
        #pragma unroll
        for (int ni = 0; ni < 4; ni++) {
            float c0 = acc[mi][ni][0], c1 = acc[mi][ni][1];
            float c2 = acc[mi][ni][2], c3 = acc[mi][ni][3];
            float v0 = __shfl_xor_sync(0xffffffffu, c0, 1);
            float v1 = __shfl_xor_sync(0xffffffffu, c1, 1);
            float v2 = __shfl_xor_sync(0xffffffffu, c2, 1);
            float v3 = __shfl_xor_sync(0xffffffffu, c3, 1);
            float F = odd ? v2 : c0;
            float I = odd ? v3 : c1;
            float G = odd ? c2 : v0;
            float O = odd ? c3 : v1;

            size_t idx = (size_t)row * H_DIM + nout[ni];
            float cp = c_prev[idx];
            float fg = 1.0f / (1.0f + expf(-(F + biasF[ni])));
            float ig = 1.0f / (1.0f + expf(-(I + biasI[ni])));
            float gg = tanhf(G + biasG[ni]);
            float og = 1.0f / (1.0f + expf(-(O + biasO[ni])));
            float cn = fg * cp + ig * gg;
            c_out[idx] = cn;
            h_out[idx] = og * tanhf(cn);
        }
    }
}

// ---------------- launch ----------------
extern "C" void kernel_launch(void* const* d_in, const int* in_sizes, int n_in,
                              void* d_out, int out_size) {
    const float* x      = (const float*)d_in[0];
    const float* h_prev = (const float*)d_in[1];
    const float* c_prev = (const float*)d_in[2];
    const float* Wf     = (const float*)d_in[3];
    const float* bf     = (const float*)d_in[4];
    const float* Wi     = (const float*)d_in[5];
    const float* bi     = (const float*)d_in[6];
    const float* Wg     = (const float*)d_in[7];
    const float* bg     = (const float*)d_in[8];
    const float* Wo     = (const float*)d_in[9];
    const float* bo     = (const float*)d_in[10];

    float* out   = (float*)d_out;
    float* h_out = out;
    float* c_out = out + (size_t)B_DIM * H_DIM;

    cudaFuncSetAttribute(lstm_gemm_kernel,
                         cudaFuncAttributeMaxDynamicSharedMemorySize, SMEM_TOTAL);

    conv_a_kernel<<<B_DIM, 256>>>(x, h_prev);
    conv_w_kernel<<<dim3(K_DIM / 32, H_DIM / 64, 4), 256>>>(Wf, Wi, Wg, Wo);
    lstm_gemm_kernel<<<dim3(4 * H_DIM / BNP, B_DIM / BM), 256, SMEM_TOTAL>>>(
        c_prev, bf, bi, bg, bo, h_out, c_out);
}

// round 4
// speedup vs baseline: 2.8244x; 1.0873x over previous
#include <cuda_runtime.h>
#include <cuda_fp16.h>
#include <math.h>

#define B_DIM 4096
#define H_DIM 1024
#define K_DIM 2048

// GEMM tiling: C[4096 m][4096 n'] where n' = n*4 + gate (gate-interleaved)
#define BM 128
#define BNP 128
#define BK 64                 // k per stage
#define KSTAGES (K_DIM / BK)  // 32
#define NBUF 4

// ---------------- device scratch (allocation-free rule: __device__ globals) ----
__device__ __align__(1024) __half g_Ah[(size_t)B_DIM * K_DIM];
__device__ __align__(1024) __half g_Al[(size_t)B_DIM * K_DIM];
__device__ __align__(1024) __half g_Bh[(size_t)4 * H_DIM * K_DIM];

// ---------------- helpers ----------------
__device__ __forceinline__ unsigned smem_u32(const void* p) {
    unsigned a;
    asm("{ .reg .u64 t; cvta.to.shared.u64 t, %1; cvt.u32.u64 %0, t; }" : "=r"(a) : "l"(p));
    return a;
}
__device__ __forceinline__ void cpa16(unsigned dst, const void* src) {
    asm volatile("cp.async.cg.shared.global [%0], [%1], 16;" :: "r"(dst), "l"(src) : "memory");
}
#define CPA_COMMIT() asm volatile("cp.async.commit_group;" ::: "memory")
#define CPA_WAIT2()  asm volatile("cp.async.wait_group 2;" ::: "memory")
#define CPA_WAIT0()  asm volatile("cp.async.wait_group 0;" ::: "memory")

__device__ __forceinline__ void ldsm4(unsigned &r0, unsigned &r1, unsigned &r2, unsigned &r3,
                                      unsigned addr) {
    asm volatile("ldmatrix.sync.aligned.m8n8.x4.shared.b16 {%0,%1,%2,%3}, [%4];"
                 : "=r"(r0), "=r"(r1), "=r"(r2), "=r"(r3) : "r"(addr));
}
__device__ __forceinline__ void mma16816(float* c, const unsigned* a, const unsigned* b) {
    asm volatile(
        "mma.sync.aligned.m16n8k16.row.col.f32.f16.f16.f32 "
        "{%0,%1,%2,%3}, {%4,%5,%6,%7}, {%8,%9}, {%0,%1,%2,%3};"
        : "+f"(c[0]), "+f"(c[1]), "+f"(c[2]), "+f"(c[3])
        : "r"(a[0]), "r"(a[1]), "r"(a[2]), "r"(a[3]), "r"(b[0]), "r"(b[1]));
}

// ---------------- merged conversion kernel ----------------
// blocks [0, 4096): A split rows;  [4096, 8192): W convert+transpose
__global__ __launch_bounds__(256) void conv_kernel(
    const float* __restrict__ x, const float* __restrict__ h_prev,
    const float* __restrict__ Wf, const float* __restrict__ Wi,
    const float* __restrict__ Wg, const float* __restrict__ Wo)
{
    __shared__ float s[32][65];
    int bid = blockIdx.x, t = threadIdx.x;
    if (bid < B_DIM) {
        // ---- A split: row bid, fp32 -> (Ah, Al) fp16 ----
        int k = t * 8;
        const float* src = (k < H_DIM) ? (x + (size_t)bid * H_DIM + k)
                                       : (h_prev + (size_t)bid * H_DIM + (k - H_DIM));
        float4 v0 = *reinterpret_cast<const float4*>(src);
        float4 v1 = *reinterpret_cast<const float4*>(src + 4);
        float vs[8] = {v0.x, v0.y, v0.z, v0.w, v1.x, v1.y, v1.z, v1.w};
        __align__(16) __half hi[8], lo[8];
        #pragma unroll
        for (int j = 0; j < 8; j++) {
            hi[j] = __float2half_rn(vs[j]);
            lo[j] = __float2half_rn(vs[j] - __half2float(hi[j]));
        }
        *reinterpret_cast<uint4*>(g_Ah + (size_t)bid * K_DIM + k) = *reinterpret_cast<uint4*>(hi);
        *reinterpret_cast<uint4*>(g_Al + (size_t)bid * K_DIM + k) = *reinterpret_cast<uint4*>(lo);
    } else {
        // ---- W: [k][n] fp32 -> BT[(n*4+g)][k] fp16 ----
        int w = bid - B_DIM;
        int k0 = (w & 63) * 32;
        int n0 = ((w >> 6) & 15) * 64;
        int g  = w >> 10;
        const float* W = (g == 0) ? Wf : (g == 1) ? Wi : (g == 2) ? Wg : Wo;
        #pragma unroll
        for (int i = 0; i < 8; i++) {
            int idx = t + i * 256;
            int kr = idx >> 6, nc = idx & 63;
            s[kr][nc] = W[(size_t)(k0 + kr) * H_DIM + n0 + nc];
        }
        __syncthreads();
        #pragma unroll
        for (int i = 0; i < 8; i++) {
            int idx = t + i * 256;
            int nn = idx >> 5, kk = idx & 31;
            g_Bh[(size_t)((n0 + nn) * 4 + g) * K_DIM + k0 + kk] = __float2half_rn(s[kk][nn]);
        }
    }
}

// ---------------- smem stage layout ----------------
// 3 tiles/stage, each 128 rows x 128B (BK=64 fp16). Swizzle: chunk c (16B) at
// phys = c ^ (row & 7).
#define OFF_AH 0
#define OFF_AL (16 * 1024)
#define OFF_BH (32 * 1024)
#define STAGE_BYTES (48 * 1024)
#define SMEM_TOTAL (NBUF * STAGE_BYTES)

__device__ __forceinline__ void load_stage(unsigned base, int s, int m0, int np0, int t) {
    int r = t >> 1;
    int c0 = (t & 1) * 4;
    unsigned rowoff = (unsigned)r * 128;
    unsigned sw = (unsigned)(r & 7);
    const __half* pAh = g_Ah + (size_t)(m0 + r) * K_DIM + s * BK + c0 * 8;
    const __half* pAl = g_Al + (size_t)(m0 + r) * K_DIM + s * BK + c0 * 8;
    const __half* pBh = g_Bh + (size_t)(np0 + r) * K_DIM + s * BK + c0 * 8;
    #pragma unroll
    for (int j = 0; j < 4; j++) {
        unsigned phys = ((unsigned)(c0 + j) ^ sw) * 16;
        cpa16(base + OFF_AH + rowoff + phys, pAh + j * 8);
        cpa16(base + OFF_AL + rowoff + phys, pAl + j * 8);
        cpa16(base + OFF_BH + rowoff + phys, pBh + j * 8);
    }
}

// ---------------- GEMM + fused LSTM epilogue ----------------
__global__ __launch_bounds__(256) void lstm_gemm_kernel(
    const float* __restrict__ c_prev,
    const float* __restrict__ bfp, const float* __restrict__ bip,
    const float* __restrict__ bgp, const float* __restrict__ bop,
    float* __restrict__ h_out, float* __restrict__ c_out)
{
    extern __shared__ char smem[];
    unsigned sb = smem_u32(smem);
    const int t = threadIdx.x;
    const int w = t >> 5, lane = t & 31;
    const int m0  = blockIdx.y * BM;
    const int np0 = blockIdx.x * BNP;

    const int wm = (w >> 2) * 64;
    const int wn = (w & 3) * 32;

    // A ldmatrix lane mapping
    const int lr = lane & 15;
    const int lc = lane >> 4;
    const unsigned swA = (unsigned)(lr & 7);
    // B ldmatrix x4-pair lane mapping: mid selects (niSel, k-sub)
    const int lb    = lane & 7;
    const int mid   = lane >> 3;
    const int niSel = mid >> 1;
    const int msub  = mid & 1;
    const unsigned swB = (unsigned)lb;

    unsigned aRow[4], bRowP[2];
    #pragma unroll
    for (int mi = 0; mi < 4; mi++) aRow[mi] = (unsigned)(wm + mi * 16 + lr) * 128;
    #pragma unroll
    for (int p = 0; p < 2; p++) bRowP[p] = (unsigned)(wn + (p * 2 + niSel) * 8 + lb) * 128;

    // accumulators initialized with biases (col-mapped), shared across mi
    const int tg = lane & 3;
    float acc[4][4][4];
    #pragma unroll
    for (int ni = 0; ni < 4; ni++) {
        int col0 = np0 + wn + ni * 8 + tg * 2;
        float b0, b1;
        {
            int g = col0 & 3, n = col0 >> 2;
            const float* p = (g == 0) ? bfp : (g == 1) ? bip : (g == 2) ? bgp : bop;
            b0 = p[n];
        }
        {
            int c1 = col0 + 1;
            int g = c1 & 3, n = c1 >> 2;
            const float* p = (g == 0) ? bfp : (g == 1) ? bip : (g == 2) ? bgp : bop;
            b1 = p[n];
        }
        #pragma unroll
        for (int mi = 0; mi < 4; mi++) {
            acc[mi][ni][0] = b0; acc[mi][ni][1] = b1;
            acc[mi][ni][2] = b0; acc[mi][ni][3] = b1;
        }
    }

    // prologue: 3 stages in flight
    load_stage(sb + 0 * STAGE_BYTES, 0, m0, np0, t); CPA_COMMIT();
    load_stage(sb + 1 * STAGE_BYTES, 1, m0, np0, t); CPA_COMMIT();
    load_stage(sb + 2 * STAGE_BYTES, 2, m0, np0, t); CPA_COMMIT();

    for (int s = 0; s < KSTAGES; s++) {
        if (s < KSTAGES - 2) CPA_WAIT2(); else CPA_WAIT0();
        __syncthreads();
        if (s + 3 < KSTAGES) {
            load_stage(sb + (unsigned)((s + 3) & 3) * STAGE_BYTES, s + 3, m0, np0, t);
            CPA_COMMIT();
        }
        unsigned base = sb + (unsigned)(s & 3) * STAGE_BYTES;

        #pragma unroll
        for (int k16 = 0; k16 < 4; k16++) {
            const unsigned cA = ((unsigned)(k16 * 2 + lc)   ^ swA) * 16;
            const unsigned cB = ((unsigned)(k16 * 2 + msub) ^ swB) * 16;

            unsigned bh[4][2];
            ldsm4(bh[0][0], bh[0][1], bh[1][0], bh[1][1], base + OFF_BH + bRowP[0] + cB);
            ldsm4(bh[2][0], bh[2][1], bh[3][0], bh[3][1], base + OFF_BH + bRowP[1] + cB);

            #pragma unroll
            for (int mi = 0; mi < 4; mi++) {
                unsigned ah[4], al[4];
                ldsm4(ah[0], ah[1], ah[2], ah[3], base + OFF_AH + aRow[mi] + cA);
                ldsm4(al[0], al[1], al[2], al[3], base + OFF_AL + aRow[mi] + cA);
                #pragma unroll
                for (int ni = 0; ni < 4; ni++) {
                    mma16816(acc[mi][ni], ah, bh[ni]);
                    mma16816(acc[mi][ni], al, bh[ni]);
                }
            }
        }
    }

    // ---- fused LSTM epilogue (biases already in acc) ----
    const int g8   = lane >> 2;
    const int odd  = tg & 1;
    const int nsel = tg >> 1;
    const int nwbase = blockIdx.x * 32 + (w & 3) * 8;

    #pragma unroll
    for (int mi = 0; mi < 4; mi++) {
        const int rbase = m0 + wm + mi * 16 + g8;
        const int row = rbase + (odd ? 8 : 0);
        #pragma unroll
        for (int ni = 0; ni < 4; ni++) {
            const int nout = nwbase + ni * 2 + nsel;
            float c0 = acc[mi][ni][0], c1 = acc[mi][ni][1];
            float c2 = acc[mi][ni][2], c3 = acc[mi][ni][3];
            float v0 = __shfl_xor_sync(0xffffffffu, c0, 1);
            float v1 = __shfl_xor_sync(0xffffffffu, c1, 1);
            float v2 = __shfl_xor_sync(0xffffffffu, c2, 1);
            float v3 = __shfl_xor_sync(0xffffffffu, c3, 1);
            float F = odd ? v2 : c0;
            float I = odd ? v3 : c1;
            float G = odd ? c2 : v0;
            float O = odd ? c3 : v1;

            size_t idx = (size_t)row * H_DIM + nout;
            float cp = c_prev[idx];
            float fg = 1.0f / (1.0f + expf(-F));
            float ig = 1.0f / (1.0f + expf(-I));
            float gg = tanhf(G);
            float og = 1.0f / (1.0f + expf(-O));
            float cn = fg * cp + ig * gg;
            c_out[idx] = cn;
            h_out[idx] = og * tanhf(cn);
        }
    }
}

// ---------------- launch ----------------
extern "C" void kernel_launch(void* const* d_in, const int* in_sizes, int n_in,
                              void* d_out, int out_size) {
    const float* x      = (const float*)d_in[0];
    const float* h_prev = (const float*)d_in[1];
    const float* c_prev = (const float*)d_in[2];
    const float* Wf     = (const float*)d_in[3];
    const float* bf     = (const float*)d_in[4];
    const float* Wi     = (const float*)d_in[5];
    const float* bi     = (const float*)d_in[6];
    const float* Wg     = (const float*)d_in[7];
    const float* bg     = (const float*)d_in[8];
    const float* Wo     = (const float*)d_in[9];
    const float* bo     = (const float*)d_in[10];

    float* out   = (float*)d_out;
    float* h_out = out;
    float* c_out = out + (size_t)B_DIM * H_DIM;

    cudaFuncSetAttribute(lstm_gemm_kernel,
                         cudaFuncAttributeMaxDynamicSharedMemorySize, SMEM_TOTAL);

    conv_kernel<<<2 * B_DIM, 256>>>(x, h_prev, Wf, Wi, Wg, Wo);
    lstm_gemm_kernel<<<dim3(4 * H_DIM / BNP, B_DIM / BM), 256, SMEM_TOTAL>>>(
        c_prev, bf, bi, bg, bo, h_out, c_out);
}

// round 5
// speedup vs baseline: 3.5342x; 1.2513x over previous
#include <cuda_runtime.h>
#include <cuda_fp16.h>
#include <math.h>

#define B_DIM 4096
#define H_DIM 1024
#define K_DIM 2048

// GEMM tiling: C[4096 m][4096 n'] where n' = n*4 + gate (gate-interleaved)
#define BM 128
#define BNP 128
#define BK 32                 // k per stage
#define KSTAGES (K_DIM / BK)  // 64
#define NBUF 4

// ---------------- device scratch (allocation-free rule: __device__ globals) ----
__device__ __align__(1024) __half g_Ah[(size_t)B_DIM * K_DIM];
__device__ __align__(1024) __half g_Al[(size_t)B_DIM * K_DIM];
__device__ __align__(1024) __half g_Bh[(size_t)4 * H_DIM * K_DIM];

// ---------------- helpers ----------------
__device__ __forceinline__ unsigned smem_u32(const void* p) {
    unsigned a;
    asm("{ .reg .u64 t; cvta.to.shared.u64 t, %1; cvt.u32.u64 %0, t; }" : "=r"(a) : "l"(p));
    return a;
}
__device__ __forceinline__ void cpa16(unsigned dst, const void* src) {
    asm volatile("cp.async.cg.shared.global [%0], [%1], 16;" :: "r"(dst), "l"(src) : "memory");
}
#define CPA_COMMIT() asm volatile("cp.async.commit_group;" ::: "memory")
#define CPA_WAIT2()  asm volatile("cp.async.wait_group 2;" ::: "memory")
#define CPA_WAIT0()  asm volatile("cp.async.wait_group 0;" ::: "memory")

__device__ __forceinline__ void ldsm4(unsigned &r0, unsigned &r1, unsigned &r2, unsigned &r3,
                                      unsigned addr) {
    asm volatile("ldmatrix.sync.aligned.m8n8.x4.shared.b16 {%0,%1,%2,%3}, [%4];"
                 : "=r"(r0), "=r"(r1), "=r"(r2), "=r"(r3) : "r"(addr));
}
__device__ __forceinline__ void mma16816(float* c, const unsigned* a, const unsigned* b) {
    asm volatile(
        "mma.sync.aligned.m16n8k16.row.col.f32.f16.f16.f32 "
        "{%0,%1,%2,%3}, {%4,%5,%6,%7}, {%8,%9}, {%0,%1,%2,%3};"
        : "+f"(c[0]), "+f"(c[1]), "+f"(c[2]), "+f"(c[3])
        : "r"(a[0]), "r"(a[1]), "r"(a[2]), "r"(a[3]), "r"(b[0]), "r"(b[1]));
}

// ---------------- merged conversion kernel ----------------
// blocks [0, 4096): A split rows;  [4096, 8192): W convert+transpose
__global__ __launch_bounds__(256) void conv_kernel(
    const float* __restrict__ x, const float* __restrict__ h_prev,
    const float* __restrict__ Wf, const float* __restrict__ Wi,
    const float* __restrict__ Wg, const float* __restrict__ Wo)
{
    __shared__ float s[32][65];
    int bid = blockIdx.x, t = threadIdx.x;
    if (bid < B_DIM) {
        int k = t * 8;
        const float* src = (k < H_DIM) ? (x + (size_t)bid * H_DIM + k)
                                       : (h_prev + (size_t)bid * H_DIM + (k - H_DIM));
        float4 v0 = *reinterpret_cast<const float4*>(src);
        float4 v1 = *reinterpret_cast<const float4*>(src + 4);
        float vs[8] = {v0.x, v0.y, v0.z, v0.w, v1.x, v1.y, v1.z, v1.w};
        __align__(16) __half hi[8], lo[8];
        #pragma unroll
        for (int j = 0; j < 8; j++) {
            hi[j] = __float2half_rn(vs[j]);
            lo[j] = __float2half_rn(vs[j] - __half2float(hi[j]));
        }
        *reinterpret_cast<uint4*>(g_Ah + (size_t)bid * K_DIM + k) = *reinterpret_cast<uint4*>(hi);
        *reinterpret_cast<uint4*>(g_Al + (size_t)bid * K_DIM + k) = *reinterpret_cast<uint4*>(lo);
    } else {
        int w = bid - B_DIM;
        int k0 = (w & 63) * 32;
        int n0 = ((w >> 6) & 15) * 64;
        int g  = w >> 10;
        const float* W = (g == 0) ? Wf : (g == 1) ? Wi : (g == 2) ? Wg : Wo;
        #pragma unroll
        for (int i = 0; i < 8; i++) {
            int idx = t + i * 256;
            int kr = idx >> 6, nc = idx & 63;
            s[kr][nc] = W[(size_t)(k0 + kr) * H_DIM + n0 + nc];
        }
        __syncthreads();
        #pragma unroll
        for (int i = 0; i < 8; i++) {
            int idx = t + i * 256;
            int nn = idx >> 5, kk = idx & 31;
            g_Bh[(size_t)((n0 + nn) * 4 + g) * K_DIM + k0 + kk] = __float2half_rn(s[kk][nn]);
        }
    }
}

// ---------------- smem stage layout ----------------
// 3 tiles/stage, each 128 rows x 64B (BK=32 fp16). Swizzle: 16B chunk c at
// phys = c ^ ((row>>1)&3).
#define OFF_AH 0
#define OFF_AL (8 * 1024)
#define OFF_BH (16 * 1024)
#define STAGE_BYTES (24 * 1024)
#define SMEM_TOTAL (NBUF * STAGE_BYTES)   // 96 KB -> 2 CTAs/SM

__device__ __forceinline__ void load_stage(unsigned base, int s, int m0, int np0, int t) {
    int r = t >> 1;
    int cpair = (t & 1) * 2;
    unsigned rowoff = (unsigned)r * 64;
    unsigned sw = (unsigned)((r >> 1) & 3);
    const __half* pAh = g_Ah + (size_t)(m0 + r) * K_DIM + s * BK + cpair * 8;
    const __half* pAl = g_Al + (size_t)(m0 + r) * K_DIM + s * BK + cpair * 8;
    const __half* pBh = g_Bh + (size_t)(np0 + r) * K_DIM + s * BK + cpair * 8;
    #pragma unroll
    for (int j = 0; j < 2; j++) {
        unsigned phys = ((unsigned)(cpair + j) ^ sw) * 16;
        cpa16(base + OFF_AH + rowoff + phys, pAh + j * 8);
        cpa16(base + OFF_AL + rowoff + phys, pAl + j * 8);
        cpa16(base + OFF_BH + rowoff + phys, pBh + j * 8);
    }
}

// ---------------- GEMM + fused LSTM epilogue ----------------
__global__ __launch_bounds__(256, 2) void lstm_gemm_kernel(
    const float* __restrict__ c_prev,
    const float* __restrict__ bfp, const float* __restrict__ bip,
    const float* __restrict__ bgp, const float* __restrict__ bop,
    float* __restrict__ h_out, float* __restrict__ c_out)
{
    extern __shared__ char smem[];
    unsigned sb = smem_u32(smem);
    const int t = threadIdx.x;
    const int w = t >> 5, lane = t & 31;
    const int m0  = blockIdx.y * BM;
    const int np0 = blockIdx.x * BNP;

    const int wm = (w >> 2) * 64;
    const int wn = (w & 3) * 32;

    // A ldmatrix lane mapping (64B rows)
    const int lr = lane & 15;
    const int lc = lane >> 4;
    const unsigned swA = (unsigned)((lr >> 1) & 3);
    // B ldmatrix x4-pair lane mapping
    const int lb    = lane & 7;
    const int mid   = lane >> 3;
    const int niSel = mid >> 1;
    const int msub  = mid & 1;
    const unsigned swB = (unsigned)((lb >> 1) & 3);

    unsigned aRow[4], bRowP[2];
    #pragma unroll
    for (int mi = 0; mi < 4; mi++) aRow[mi] = (unsigned)(wm + mi * 16 + lr) * 64;
    #pragma unroll
    for (int p = 0; p < 2; p++) bRowP[p] = (unsigned)(wn + (p * 2 + niSel) * 8 + lb) * 64;

    // accumulators initialized with biases (col-mapped)
    const int tg = lane & 3;
    float acc[4][4][4];
    #pragma unroll
    for (int ni = 0; ni < 4; ni++) {
        int col0 = np0 + wn + ni * 8 + tg * 2;
        float b0, b1;
        {
            int g = col0 & 3, n = col0 >> 2;
            const float* p = (g == 0) ? bfp : (g == 1) ? bip : (g == 2) ? bgp : bop;
            b0 = p[n];
        }
        {
            int c1 = col0 + 1;
            int g = c1 & 3, n = c1 >> 2;
            const float* p = (g == 0) ? bfp : (g == 1) ? bip : (g == 2) ? bgp : bop;
            b1 = p[n];
        }
        #pragma unroll
        for (int mi = 0; mi < 4; mi++) {
            acc[mi][ni][0] = b0; acc[mi][ni][1] = b1;
            acc[mi][ni][2] = b0; acc[mi][ni][3] = b1;
        }
    }

    load_stage(sb + 0 * STAGE_BYTES, 0, m0, np0, t); CPA_COMMIT();
    load_stage(sb + 1 * STAGE_BYTES, 1, m0, np0, t); CPA_COMMIT();
    load_stage(sb + 2 * STAGE_BYTES, 2, m0, np0, t); CPA_COMMIT();

    for (int s = 0; s < KSTAGES; s++) {
        if (s < KSTAGES - 2) CPA_WAIT2(); else CPA_WAIT0();
        __syncthreads();
        if (s + 3 < KSTAGES) {
            load_stage(sb + (unsigned)((s + 3) & 3) * STAGE_BYTES, s + 3, m0, np0, t);
            CPA_COMMIT();
        }
        unsigned base = sb + (unsigned)(s & 3) * STAGE_BYTES;

        #pragma unroll
        for (int k16 = 0; k16 < 2; k16++) {
            const unsigned cA = ((unsigned)(k16 * 2 + lc)   ^ swA) * 16;
            const unsigned cB = ((unsigned)(k16 * 2 + msub) ^ swB) * 16;

            unsigned bh[4][2];
            ldsm4(bh[0][0], bh[0][1], bh[1][0], bh[1][1], base + OFF_BH + bRowP[0] + cB);
            ldsm4(bh[2][0], bh[2][1], bh[3][0], bh[3][1], base + OFF_BH + bRowP[1] + cB);

            #pragma unroll
            for (int mi = 0; mi < 4; mi++) {
                unsigned ah[4], al[4];
                ldsm4(ah[0], ah[1], ah[2], ah[3], base + OFF_AH + aRow[mi] + cA);
                ldsm4(al[0], al[1], al[2], al[3], base + OFF_AL + aRow[mi] + cA);
                #pragma unroll
                for (int ni = 0; ni < 4; ni++) {
                    mma16816(acc[mi][ni], ah, bh[ni]);
                    mma16816(acc[mi][ni], al, bh[ni]);
                }
            }
        }
    }

    // ---- fused LSTM epilogue (biases already in acc) ----
    const int g8   = lane >> 2;
    const int odd  = tg & 1;
    const int nsel = tg >> 1;
    const int nwbase = blockIdx.x * 32 + (w & 3) * 8;

    #pragma unroll
    for (int mi = 0; mi < 4; mi++) {
        const int rbase = m0 + wm + mi * 16 + g8;
        const int row = rbase + (odd ? 8 : 0);
        #pragma unroll
        for (int ni = 0; ni < 4; ni++) {
            const int nout = nwbase + ni * 2 + nsel;
            float c0 = acc[mi][ni][0], c1 = acc[mi][ni][1];
            float c2 = acc[mi][ni][2], c3 = acc[mi][ni][3];
            float v0 = __shfl_xor_sync(0xffffffffu, c0, 1);
            float v1 = __shfl_xor_sync(0xffffffffu, c1, 1);
            float v2 = __shfl_xor_sync(0xffffffffu, c2, 1);
            float v3 = __shfl_xor_sync(0xffffffffu, c3, 1);
            float F = odd ? v2 : c0;
            float I = odd ? v3 : c1;
            float G = odd ? c2 : v0;
            float O = odd ? c3 : v1;

            size_t idx = (size_t)row * H_DIM + nout;
            float cp = c_prev[idx];
            float fg = 1.0f / (1.0f + expf(-F));
            float ig = 1.0f / (1.0f + expf(-I));
            float gg = tanhf(G);
            float og = 1.0f / (1.0f + expf(-O));
            float cn = fg * cp + ig * gg;
            c_out[idx] = cn;
            h_out[idx] = og * tanhf(cn);
        }
    }
}

// ---------------- launch ----------------
extern "C" void kernel_launch(void* const* d_in, const int* in_sizes, int n_in,
                              void* d_out, int out_size) {
    const float* x      = (const float*)d_in[0];
    const float* h_prev = (const float*)d_in[1];
    const float* c_prev = (const float*)d_in[2];
    const float* Wf     = (const float*)d_in[3];
    const float* bf     = (const float*)d_in[4];
    const float* Wi     = (const float*)d_in[5];
    const float* bi     = (const float*)d_in[6];
    const float* Wg     = (const float*)d_in[7];
    const float* bg     = (const float*)d_in[8];
    const float* Wo     = (const float*)d_in[9];
    const float* bo     = (const float*)d_in[10];

    float* out   = (float*)d_out;
    float* h_out = out;
    float* c_out = out + (size_t)B_DIM * H_DIM;

    cudaFuncSetAttribute(lstm_gemm_kernel,
                         cudaFuncAttributeMaxDynamicSharedMemorySize, SMEM_TOTAL);

    conv_kernel<<<2 * B_DIM, 256>>>(x, h_prev, Wf, Wi, Wg, Wo);
    lstm_gemm_kernel<<<dim3(4 * H_DIM / BNP, B_DIM / BM), 256, SMEM_TOTAL>>>(
        c_prev, bf, bi, bg, bo, h_out, c_out);
}

// round 6
// speedup vs baseline: 5.5983x; 1.5840x over previous
#include <cuda_runtime.h>
#include <cuda_fp16.h>
#include <math.h>

#define B_DIM 4096
#define H_DIM 1024
#define K_DIM 2048

// GEMM tiling: C[4096 m][4096 n'] where n' = n*4 + gate (gate-interleaved)
#define BM 128
#define BNP 128
#define BK 32                 // k per stage
#define KSTAGES (K_DIM / BK)  // 64
#define NBUF 6

// ---------------- device scratch (allocation-free rule: __device__ globals) ----
__device__ __align__(1024) __half g_Ah[(size_t)B_DIM * K_DIM];
__device__ __align__(1024) __half g_Bh[(size_t)4 * H_DIM * K_DIM];

// ---------------- helpers ----------------
__device__ __forceinline__ unsigned smem_u32(const void* p) {
    unsigned a;
    asm("{ .reg .u64 t; cvta.to.shared.u64 t, %1; cvt.u32.u64 %0, t; }" : "=r"(a) : "l"(p));
    return a;
}
__device__ __forceinline__ void cpa16(unsigned dst, const void* src) {
    asm volatile("cp.async.cg.shared.global [%0], [%1], 16;" :: "r"(dst), "l"(src) : "memory");
}
#define CPA_COMMIT() asm volatile("cp.async.commit_group;" ::: "memory")
#define CPA_WAIT4()  asm volatile("cp.async.wait_group 4;" ::: "memory")
#define CPA_WAIT0()  asm volatile("cp.async.wait_group 0;" ::: "memory")

__device__ __forceinline__ void ldsm4(unsigned &r0, unsigned &r1, unsigned &r2, unsigned &r3,
                                      unsigned addr) {
    asm volatile("ldmatrix.sync.aligned.m8n8.x4.shared.b16 {%0,%1,%2,%3}, [%4];"
                 : "=r"(r0), "=r"(r1), "=r"(r2), "=r"(r3) : "r"(addr));
}
__device__ __forceinline__ void mma16816(float* c, const unsigned* a, const unsigned* b) {
    asm volatile(
        "mma.sync.aligned.m16n8k16.row.col.f32.f16.f16.f32 "
        "{%0,%1,%2,%3}, {%4,%5,%6,%7}, {%8,%9}, {%0,%1,%2,%3};"
        : "+f"(c[0]), "+f"(c[1]), "+f"(c[2]), "+f"(c[3])
        : "r"(a[0]), "r"(a[1]), "r"(a[2]), "r"(a[3]), "r"(b[0]), "r"(b[1]));
}

// ---------------- merged conversion kernel ----------------
// blocks [0, 4096): A rows fp32->fp16;  [4096, 8192): W convert+transpose
__global__ __launch_bounds__(256) void conv_kernel(
    const float* __restrict__ x, const float* __restrict__ h_prev,
    const float* __restrict__ Wf, const float* __restrict__ Wi,
    const float* __restrict__ Wg, const float* __restrict__ Wo)
{
    __shared__ float s[32][65];
    int bid = blockIdx.x, t = threadIdx.x;
    if (bid < B_DIM) {
        int k = t * 8;
        const float* src = (k < H_DIM) ? (x + (size_t)bid * H_DIM + k)
                                       : (h_prev + (size_t)bid * H_DIM + (k - H_DIM));
        float4 v0 = *reinterpret_cast<const float4*>(src);
        float4 v1 = *reinterpret_cast<const float4*>(src + 4);
        float vs[8] = {v0.x, v0.y, v0.z, v0.w, v1.x, v1.y, v1.z, v1.w};
        __align__(16) __half hi[8];
        #pragma unroll
        for (int j = 0; j < 8; j++) hi[j] = __float2half_rn(vs[j]);
        *reinterpret_cast<uint4*>(g_Ah + (size_t)bid * K_DIM + k) = *reinterpret_cast<uint4*>(hi);
    } else {
        int w = bid - B_DIM;
        int k0 = (w & 63) * 32;
        int n0 = ((w >> 6) & 15) * 64;
        int g  = w >> 10;
        const float* W = (g == 0) ? Wf : (g == 1) ? Wi : (g == 2) ? Wg : Wo;
        #pragma unroll
        for (int i = 0; i < 8; i++) {
            int idx = t + i * 256;
            int kr = idx >> 6, nc = idx & 63;
            s[kr][nc] = W[(size_t)(k0 + kr) * H_DIM + n0 + nc];
        }
        __syncthreads();
        #pragma unroll
        for (int i = 0; i < 8; i++) {
            int idx = t + i * 256;
            int nn = idx >> 5, kk = idx & 31;
            g_Bh[(size_t)((n0 + nn) * 4 + g) * K_DIM + k0 + kk] = __float2half_rn(s[kk][nn]);
        }
    }
}

// ---------------- smem stage layout ----------------
// 2 tiles/stage, each 128 rows x 64B (BK=32 fp16). Swizzle: 16B chunk c at
// phys = c ^ ((row>>1)&3).
#define OFF_AH 0
#define OFF_BH (8 * 1024)
#define STAGE_BYTES (16 * 1024)
#define SMEM_TOTAL (NBUF * STAGE_BYTES)   // 96 KB -> 2 CTAs/SM

__device__ __forceinline__ void load_stage(unsigned base, int s, int m0, int np0, int t) {
    int r = t >> 1;
    int cpair = (t & 1) * 2;
    unsigned rowoff = (unsigned)r * 64;
    unsigned sw = (unsigned)((r >> 1) & 3);
    const __half* pAh = g_Ah + (size_t)(m0 + r) * K_DIM + s * BK + cpair * 8;
    const __half* pBh = g_Bh + (size_t)(np0 + r) * K_DIM + s * BK + cpair * 8;
    #pragma unroll
    for (int j = 0; j < 2; j++) {
        unsigned phys = ((unsigned)(cpair + j) ^ sw) * 16;
        cpa16(base + OFF_AH + rowoff + phys, pAh + j * 8);
        cpa16(base + OFF_BH + rowoff + phys, pBh + j * 8);
    }
}

// ---------------- GEMM + fused LSTM epilogue ----------------
__global__ __launch_bounds__(256, 2) void lstm_gemm_kernel(
    const float* __restrict__ c_prev,
    const float* __restrict__ bfp, const float* __restrict__ bip,
    const float* __restrict__ bgp, const float* __restrict__ bop,
    float* __restrict__ h_out, float* __restrict__ c_out)
{
    extern __shared__ char smem[];
    unsigned sb = smem_u32(smem);
    const int t = threadIdx.x;
    const int w = t >> 5, lane = t & 31;
    const int m0  = blockIdx.y * BM;
    const int np0 = blockIdx.x * BNP;

    const int wm = (w >> 2) * 64;
    const int wn = (w & 3) * 32;

    // A ldmatrix lane mapping (64B rows)
    const int lr = lane & 15;
    const int lc = lane >> 4;
    const unsigned swA = (unsigned)((lr >> 1) & 3);
    // B ldmatrix x4-pair lane mapping
    const int lb    = lane & 7;
    const int mid   = lane >> 3;
    const int niSel = mid >> 1;
    const int msub  = mid & 1;
    const unsigned swB = (unsigned)((lb >> 1) & 3);

    unsigned aRow[4], bRowP[2];
    #pragma unroll
    for (int mi = 0; mi < 4; mi++) aRow[mi] = (unsigned)(wm + mi * 16 + lr) * 64;
    #pragma unroll
    for (int p = 0; p < 2; p++) bRowP[p] = (unsigned)(wn + (p * 2 + niSel) * 8 + lb) * 64;

    // accumulators initialized with biases (col-mapped)
    const int tg = lane & 3;
    float acc[4][4][4];
    #pragma unroll
    for (int ni = 0; ni < 4; ni++) {
        int col0 = np0 + wn + ni * 8 + tg * 2;
        float b0, b1;
        {
            int g = col0 & 3, n = col0 >> 2;
            const float* p = (g == 0) ? bfp : (g == 1) ? bip : (g == 2) ? bgp : bop;
            b0 = p[n];
        }
        {
            int c1 = col0 + 1;
            int g = c1 & 3, n = c1 >> 2;
            const float* p = (g == 0) ? bfp : (g == 1) ? bip : (g == 2) ? bgp : bop;
            b1 = p[n];
        }
        #pragma unroll
        for (int mi = 0; mi < 4; mi++) {
            acc[mi][ni][0] = b0; acc[mi][ni][1] = b1;
            acc[mi][ni][2] = b0; acc[mi][ni][3] = b1;
        }
    }

    // prologue: 5 stages in flight
    #pragma unroll
    for (int p = 0; p < 5; p++) {
        load_stage(sb + (unsigned)p * STAGE_BYTES, p, m0, np0, t);
        CPA_COMMIT();
    }

    unsigned bufIdx = 0;
    for (int s = 0; s < KSTAGES; s++) {
        if (s < KSTAGES - 4) CPA_WAIT4(); else CPA_WAIT0();
        __syncthreads();
        if (s + 5 < KSTAGES) {
            unsigned pb = bufIdx + 5; if (pb >= NBUF) pb -= NBUF;
            load_stage(sb + pb * STAGE_BYTES, s + 5, m0, np0, t);
            CPA_COMMIT();
        }
        unsigned base = sb + bufIdx * STAGE_BYTES;
        if (++bufIdx == NBUF) bufIdx = 0;

        #pragma unroll
        for (int k16 = 0; k16 < 2; k16++) {
            const unsigned cA = ((unsigned)(k16 * 2 + lc)   ^ swA) * 16;
            const unsigned cB = ((unsigned)(k16 * 2 + msub) ^ swB) * 16;

            unsigned bh[4][2];
            ldsm4(bh[0][0], bh[0][1], bh[1][0], bh[1][1], base + OFF_BH + bRowP[0] + cB);
            ldsm4(bh[2][0], bh[2][1], bh[3][0], bh[3][1], base + OFF_BH + bRowP[1] + cB);

            #pragma unroll
            for (int mi = 0; mi < 4; mi++) {
                unsigned ah[4];
                ldsm4(ah[0], ah[1], ah[2], ah[3], base + OFF_AH + aRow[mi] + cA);
                #pragma unroll
                for (int ni = 0; ni < 4; ni++)
                    mma16816(acc[mi][ni], ah, bh[ni]);
            }
        }
    }

    // ---- fused LSTM epilogue (biases already in acc) ----
    const int g8   = lane >> 2;
    const int odd  = tg & 1;
    const int nsel = tg >> 1;
    const int nwbase = blockIdx.x * 32 + (w & 3) * 8;

    #pragma unroll
    for (int mi = 0; mi < 4; mi++) {
        const int rbase = m0 + wm + mi * 16 + g8;
        const int row = rbase + (odd ? 8 : 0);
        #pragma unroll
        for (int ni = 0; ni < 4; ni++) {
            const int nout = nwbase + ni * 2 + nsel;
            float c0 = acc[mi][ni][0], c1 = acc[mi][ni][1];
            float c2 = acc[mi][ni][2], c3 = acc[mi][ni][3];
            float v0 = __shfl_xor_sync(0xffffffffu, c0, 1);
            float v1 = __shfl_xor_sync(0xffffffffu, c1, 1);
            float v2 = __shfl_xor_sync(0xffffffffu, c2, 1);
            float v3 = __shfl_xor_sync(0xffffffffu, c3, 1);
            float F = odd ? v2 : c0;
            float I = odd ? v3 : c1;
            float G = odd ? c2 : v0;
            float O = odd ? c3 : v1;

            size_t idx = (size_t)row * H_DIM + nout;
            float cp = c_prev[idx];
            float fg = 1.0f / (1.0f + expf(-F));
            float ig = 1.0f / (1.0f + expf(-I));
            float gg = tanhf(G);
            float og = 1.0f / (1.0f + expf(-O));
            float cn = fg * cp + ig * gg;
            c_out[idx] = cn;
            h_out[idx] = og * tanhf(cn);
        }
    }
}

// ---------------- launch ----------------
extern "C" void kernel_launch(void* const* d_in, const int* in_sizes, int n_in,
                              void* d_out, int out_size) {
    const float* x      = (const float*)d_in[0];
    const float* h_prev = (const float*)d_in[1];
    const float* c_prev = (const float*)d_in[2];
    const float* Wf     = (const float*)d_in[3];
    const float* bf     = (const float*)d_in[4];
    const float* Wi     = (const float*)d_in[5];
    const float* bi     = (const float*)d_in[6];
    const float* Wg     = (const float*)d_in[7];
    const float* bg     = (const float*)d_in[8];
    const float* Wo     = (const float*)d_in[9];
    const float* bo     = (const float*)d_in[10];

    float* out   = (float*)d_out;
    float* h_out = out;
    float* c_out = out + (size_t)B_DIM * H_DIM;

    cudaFuncSetAttribute(lstm_gemm_kernel,
                         cudaFuncAttributeMaxDynamicSharedMemorySize, SMEM_TOTAL);

    conv_kernel<<<2 * B_DIM, 256>>>(x, h_prev, Wf, Wi, Wg, Wo);
    lstm_gemm_kernel<<<dim3(4 * H_DIM / BNP, B_DIM / BM), 256, SMEM_TOTAL>>>(
        c_prev, bf, bi, bg, bo, h_out, c_out);
}